// round 17
// baseline (speedup 1.0000x reference)
#include <cuda_runtime.h>
#include <cstdint>

// Skeleton forward kinematics: 6d rotations -> world-space joint positions.
// angles: [B, 16, 6] f32   xyz: [1, 16, 3] f32   out: [B, 16, 3] f32
//
// Round-17: packed f32x2 — each thread computes TWO batch elements with one
// stream of fma/mul/add.rn.f32x2 (sm_103a packed fp32). Math instructions per
// element halve; dependency chains unchanged; memory ops per element same.
// Tile = 256 elements, TPB=128, thread t handles (t, t+128). Smem 24 rows x
// pitch-257 float4 (96.8 KB -> 2 blocks/SM). v11 schedule throughout.

namespace {

typedef unsigned long long ull;

constexpr int NJ   = 16;
constexpr int TPB  = 128;
constexpr int TILE = 256;                       // elements per block
constexpr int PIT  = 257;                       // float4 pitch (odd -> conflict-free)
constexpr size_t SMEM_BYTES = 24 * PIT * sizeof(float4) + 48 * sizeof(float2);

__device__ __forceinline__ ull pk(float lo, float hi) {
    ull r; asm("mov.b64 %0, {%1, %2};" : "=l"(r) : "f"(lo), "f"(hi)); return r;
}
__device__ __forceinline__ void upk(float& lo, float& hi, ull v) {
    asm("mov.b64 {%0, %1}, %2;" : "=f"(lo), "=f"(hi) : "l"(v));
}
__device__ __forceinline__ ull fma2(ull a, ull b, ull c) {
    ull d; asm("fma.rn.f32x2 %0, %1, %2, %3;" : "=l"(d) : "l"(a), "l"(b), "l"(c));
    return d;
}
__device__ __forceinline__ ull mul2(ull a, ull b) {
    ull d; asm("mul.rn.f32x2 %0, %1, %2;" : "=l"(d) : "l"(a), "l"(b)); return d;
}
__device__ __forceinline__ ull neg2(ull a) { return a ^ 0x8000000080000000ULL; }
__device__ __forceinline__ ull rsqrt2(ull a) {
    float lo, hi; upk(lo, hi, a);
    return pk(rsqrtf(lo), rsqrtf(hi));
}

// Packed 6d -> rotation (rows b1,b2,b3) for two elements at once.
__device__ __forceinline__ void rot6d2(const ull* __restrict__ a, ull R[9]) {
    ull s1 = fma2(a[0], a[0], fma2(a[1], a[1], mul2(a[2], a[2])));
    ull n1 = rsqrt2(s1);
    ull b1x = mul2(a[0], n1), b1y = mul2(a[1], n1), b1z = mul2(a[2], n1);
    ull d  = fma2(b1x, a[3], fma2(b1y, a[4], mul2(b1z, a[5])));
    ull nd = neg2(d);
    ull b2x = fma2(nd, b1x, a[3]);
    ull b2y = fma2(nd, b1y, a[4]);
    ull b2z = fma2(nd, b1z, a[5]);
    ull s2 = fma2(b2x, b2x, fma2(b2y, b2y, mul2(b2z, b2z)));
    ull n2 = rsqrt2(s2);
    b2x = mul2(b2x, n2); b2y = mul2(b2y, n2); b2z = mul2(b2z, n2);
    R[0] = b1x; R[1] = b1y; R[2] = b1z;
    R[3] = b2x; R[4] = b2y; R[5] = b2z;
    R[6] = fma2(b1y, b2z, neg2(mul2(b1z, b2y)));
    R[7] = fma2(b1z, b2x, neg2(mul2(b1x, b2z)));
    R[8] = fma2(b1x, b2y, neg2(mul2(b1y, b2x)));
}

__global__ __launch_bounds__(TPB)
void skeleton_fk_v17(const float4* __restrict__ angles4,
                     const float*  __restrict__ xyz,
                     float4* __restrict__ out4)
{
    extern __shared__ float4 sa4[];                            // [24 * PIT]
    float2* stv2f = reinterpret_cast<float2*>(sa4 + 24 * PIT); // [48] duplicated
    const ull* stv2 = reinterpret_cast<const ull*>(stv2f);

    const int t = threadIdx.x;
    const size_t eB = (size_t)blockIdx.x * TILE;

    // ---- Stage: coalesced LDG.128 -> conflict-free STS.128 ----
    const float4* __restrict__ src = angles4 + eB * 24;
#pragma unroll
    for (int k = 0; k < 48; ++k) {
        int g = t + k * TPB;                  // 0..6143
        int b = g / 24;                       // element column 0..255
        int r = g - b * 24;                   // float4 row 0..23
        sa4[r * PIT + b] = __ldg(src + g);
    }
    // Edge vectors duplicated into float2 so LDS.64 yields a packed operand.
    {
        constexpr int PARENT[15] = {0, 1, 2, 3, 4, 3, 6, 7, 8, 9, 3, 11, 12, 13, 14};
        if (t < 48) {
            float v;
            if (t < 3) v = __ldg(xyz + t);
            else {
                int i = t - 3;
                int e = i / 3, k = i - 3 * e;
                v = __ldg(xyz + 3 * (e + 1) + k) - __ldg(xyz + 3 * PARENT[e] + k);
            }
            stv2f[t] = make_float2(v, v);
        }
    }
    __syncthreads();

    // ---- Compute (v11 schedule, packed f32x2 math) ----
    {
        ull a2[12];
        ull pw[48];
        ull Rc[9], Rs[9];

        auto loadPair = [&](int j) {          // joints 2j, 2j+1 for both elems
            float4 p0 = sa4[(3 * j + 0) * PIT + t];
            float4 p1 = sa4[(3 * j + 1) * PIT + t];
            float4 p2 = sa4[(3 * j + 2) * PIT + t];
            float4 q0 = sa4[(3 * j + 0) * PIT + t + 128];
            float4 q1 = sa4[(3 * j + 1) * PIT + t + 128];
            float4 q2 = sa4[(3 * j + 2) * PIT + t + 128];
            a2[0]  = pk(p0.x, q0.x); a2[1]  = pk(p0.y, q0.y);
            a2[2]  = pk(p0.z, q0.z); a2[3]  = pk(p0.w, q0.w);
            a2[4]  = pk(p1.x, q1.x); a2[5]  = pk(p1.y, q1.y);
            a2[6]  = pk(p1.z, q1.z); a2[7]  = pk(p1.w, q1.w);
            a2[8]  = pk(p2.x, q2.x); a2[9]  = pk(p2.y, q2.y);
            a2[10] = pk(p2.z, q2.z); a2[11] = pk(p2.w, q2.w);
        };
        auto flushRow = [&](int r) {          // pw float4 row -> both columns
            float l0, h0, l1, h1, l2, h2, l3, h3;
            upk(l0, h0, pw[4 * r + 0]); upk(l1, h1, pw[4 * r + 1]);
            upk(l2, h2, pw[4 * r + 2]); upk(l3, h3, pw[4 * r + 3]);
            sa4[r * PIT + t]       = make_float4(l0, l1, l2, l3);
            sa4[r * PIT + t + 128] = make_float4(h0, h1, h2, h3);
        };
        auto step = [&](int p, int c, const ull* a6) {
            ull R[9];
            rot6d2(a6, R);
            ull Rn[9];
#pragma unroll
            for (int i = 0; i < 3; ++i)
#pragma unroll
                for (int k = 0; k < 3; ++k)
                    Rn[3 * i + k] = fma2(Rc[3 * i + 0], R[0 + k],
                                    fma2(Rc[3 * i + 1], R[3 + k],
                                    mul2(Rc[3 * i + 2], R[6 + k])));
            ull tx = stv2[3 * c + 0], ty = stv2[3 * c + 1], tz = stv2[3 * c + 2];
            pw[3 * c + 0] = fma2(Rn[0], tx, fma2(Rn[1], ty, fma2(Rn[2], tz, pw[3 * p + 0])));
            pw[3 * c + 1] = fma2(Rn[3], tx, fma2(Rn[4], ty, fma2(Rn[5], tz, pw[3 * p + 1])));
            pw[3 * c + 2] = fma2(Rn[6], tx, fma2(Rn[7], ty, fma2(Rn[8], tz, pw[3 * p + 2])));
#pragma unroll
            for (int i = 0; i < 9; ++i) Rc[i] = Rn[i];
        };

        // Root joint 0
        loadPair(0);
        rot6d2(&a2[0], Rc);
        {
            ull x = stv2[0], y = stv2[1], z = stv2[2];
            pw[0] = fma2(Rc[0], x, fma2(Rc[1], y, mul2(Rc[2], z)));
            pw[1] = fma2(Rc[3], x, fma2(Rc[4], y, mul2(Rc[5], z)));
            pw[2] = fma2(Rc[6], x, fma2(Rc[7], y, mul2(Rc[8], z)));
        }

        // Chain 0-1-2-3 (flush row r only after its angle floats consumed)
        step(0, 1, &a2[6]);  flushRow(0);
        loadPair(1);
        step(1, 2, &a2[0]);  flushRow(1);
        step(2, 3, &a2[6]);  flushRow(2);
#pragma unroll
        for (int i = 0; i < 9; ++i) Rs[i] = Rc[i];

        // Branch A: 3-4-5
        loadPair(2);
        step(3, 4, &a2[0]);
        step(4, 5, &a2[6]);  flushRow(3);

        // Branch B: 3-6-7-8-9-10
#pragma unroll
        for (int i = 0; i < 9; ++i) Rc[i] = Rs[i];
        loadPair(3);
        step(3, 6, &a2[0]);  flushRow(4);
        step(6, 7, &a2[6]);  flushRow(5);
        loadPair(4);
        step(7, 8, &a2[0]);
        step(8, 9, &a2[6]);  flushRow(6);
        loadPair(5);
        step(9, 10, &a2[0]); flushRow(7);

        // Branch C: 3-11-12-13-14-15
#pragma unroll
        for (int i = 0; i < 9; ++i) Rc[i] = Rs[i];
        step(3, 11, &a2[6]);  flushRow(8);
        loadPair(6);
        step(11, 12, &a2[0]);
        step(12, 13, &a2[6]); flushRow(9);
        loadPair(7);
        step(13, 14, &a2[0]); flushRow(10);
        step(14, 15, &a2[6]); flushRow(11);
    }

    __syncthreads();

    // ---- Gather: conflict-free LDS.128 -> coalesced STG.128 ----
    float4* __restrict__ dst = out4 + eB * 12;
#pragma unroll
    for (int k = 0; k < 24; ++k) {
        int g = t + k * TPB;                  // 0..3071
        int b = g / 12;
        int r = g - b * 12;
        dst[g] = sa4[r * PIT + b];
    }
}

// Scalar tail fallback (unused: 262144 % 256 == 0; kept for safety).
__device__ __forceinline__ void rot6d_s(const float* __restrict__ a, float R[9]) {
    float n1 = rsqrtf(a[0]*a[0] + a[1]*a[1] + a[2]*a[2]);
    float b1x = a[0]*n1, b1y = a[1]*n1, b1z = a[2]*n1;
    float d = b1x*a[3] + b1y*a[4] + b1z*a[5];
    float b2x = a[3]-d*b1x, b2y = a[4]-d*b1y, b2z = a[5]-d*b1z;
    float n2 = rsqrtf(b2x*b2x + b2y*b2y + b2z*b2z);
    b2x *= n2; b2y *= n2; b2z *= n2;
    R[0]=b1x; R[1]=b1y; R[2]=b1z;
    R[3]=b2x; R[4]=b2y; R[5]=b2z;
    R[6]=b1y*b2z-b1z*b2y; R[7]=b1z*b2x-b1x*b2z; R[8]=b1x*b2y-b1y*b2x;
}

__global__ void skeleton_fk_tail(const float* __restrict__ angles,
                                 const float* __restrict__ xyz,
                                 float* __restrict__ out,
                                 int start, int batch)
{
    int b = start + blockIdx.x * blockDim.x + threadIdx.x;
    if (b >= batch) return;
    const float* ab = angles + (size_t)b * (NJ * 6);
    float ref[NJ * 3];
#pragma unroll
    for (int i = 0; i < NJ * 3; ++i) ref[i] = __ldg(xyz + i);

    float Rw[NJ * 9], pw[NJ * 3];
    {
        float a[6];
#pragma unroll
        for (int k = 0; k < 6; ++k) a[k] = ab[k];
        rot6d_s(a, &Rw[0]);
        float x = ref[0], y = ref[1], z = ref[2];
        pw[0] = Rw[0]*x + Rw[1]*y + Rw[2]*z;
        pw[1] = Rw[3]*x + Rw[4]*y + Rw[5]*z;
        pw[2] = Rw[6]*x + Rw[7]*y + Rw[8]*z;
    }
    constexpr int PARENT[15] = {0, 1, 2, 3, 4, 3, 6, 7, 8, 9, 3, 11, 12, 13, 14};
#pragma unroll
    for (int e = 0; e < 15; ++e) {
        const int p = PARENT[e], c = e + 1;
        float a[6];
#pragma unroll
        for (int k = 0; k < 6; ++k) a[k] = ab[6 * c + k];
        float R[9]; rot6d_s(a, R);
        float tx = ref[3*c+0] - ref[3*p+0];
        float ty = ref[3*c+1] - ref[3*p+1];
        float tz = ref[3*c+2] - ref[3*p+2];
        const float* pR = &Rw[9 * p];
        float* nR = &Rw[9 * c];
#pragma unroll
        for (int i = 0; i < 3; ++i)
#pragma unroll
            for (int k = 0; k < 3; ++k)
                nR[3*i+k] = pR[3*i+0]*R[k] + pR[3*i+1]*R[3+k] + pR[3*i+2]*R[6+k];
        pw[3*c+0] = nR[0]*tx + nR[1]*ty + nR[2]*tz + pw[3*p+0];
        pw[3*c+1] = nR[3]*tx + nR[4]*ty + nR[5]*tz + pw[3*p+1];
        pw[3*c+2] = nR[6]*tx + nR[7]*ty + nR[8]*tz + pw[3*p+2];
    }
    float* o = out + (size_t)b * (NJ * 3);
#pragma unroll
    for (int i = 0; i < NJ * 3; ++i) o[i] = pw[i];
}

}  // namespace

extern "C" void kernel_launch(void* const* d_in, const int* in_sizes, int n_in,
                              void* d_out, int out_size) {
    const float* angles = (const float*)d_in[0];
    const float* xyz    = (const float*)d_in[1];
    float* out          = (float*)d_out;

    const int batch = in_sizes[0] / (NJ * 6);
    const int full  = batch / TILE;

    cudaFuncSetAttribute(skeleton_fk_v17,
                         cudaFuncAttributeMaxDynamicSharedMemorySize,
                         (int)SMEM_BYTES);

    if (full > 0) {
        skeleton_fk_v17<<<full, TPB, SMEM_BYTES>>>(
            (const float4*)angles, xyz, (float4*)out);
    }
    const int rem = batch - full * TILE;
    if (rem > 0) {
        skeleton_fk_tail<<<(rem + 127) / 128, 128>>>(angles, xyz, out,
                                                     full * TILE, batch);
    }
}